// round 1
// baseline (speedup 1.0000x reference)
#include <cuda_runtime.h>
#include <cuda_bf16.h>
#include <math.h>

// Problem constants
#define B_    4
#define C_    384
#define C3_   1152
#define CT_   1536        // 1152 qkv + 384 bs
#define HH_   128
#define WW_   128
#define P_    16384       // H*W
#define HEADS_ 8
#define CH_   48
#define BH_   32          // B*HEADS
#define SPLITS_ 16
#define SCALE_ 0.14433756729740643f  // 1/sqrt(48)

// Scratch (static device allocations; no cudaMalloc allowed)
__device__ float g_pw[(size_t)B_ * CT_ * P_];       // pointwise output
__device__ float g_dw[(size_t)B_ * CT_ * P_];       // depthwise output (q,k,v,y)
__device__ float g_attnout[(size_t)B_ * C_ * P_];   // attn @ V
__device__ float g_part[(size_t)BH_ * SPLITS_ * CH_ * CH_]; // split-K partials
__device__ float g_norms[2 * B_ * C_];              // q norms then k norms
__device__ float g_attn[(size_t)BH_ * CH_ * CH_];   // softmaxed attention

// ---------------------------------------------------------------------------
// Fused pointwise 1x1 conv GEMM: out[1536 x 16384] = Wcat[1536 x 384] * x
// Tile 64x64x16, 256 threads, 4x4 per thread.
// ---------------------------------------------------------------------------
__global__ __launch_bounds__(256) void gemm_pw_kernel(
    const float* __restrict__ x,
    const float* __restrict__ w_qkv,
    const float* __restrict__ w_bs_pw)
{
    const int b  = blockIdx.z;
    const int m0 = blockIdx.y * 64;     // output channel base
    const int n0 = blockIdx.x * 64;     // pixel base
    const int tid = threadIdx.x;
    const int tx = tid & 15, ty = tid >> 4;

    __shared__ float As[16][64];
    __shared__ float Bs[16][64];

    const float* xb = x + (size_t)b * C_ * P_;
    float acc[4][4] = {};

    for (int k0 = 0; k0 < C_; k0 += 16) {
        #pragma unroll
        for (int e = 0; e < 4; e++) {
            int idx = tid + e * 256;
            int k = idx & 15;
            int m = idx >> 4;
            int co = m0 + m;
            float wv = (co < C3_) ? w_qkv[co * C_ + k0 + k]
                                  : w_bs_pw[(co - C3_) * C_ + k0 + k];
            As[k][m] = wv;
        }
        #pragma unroll
        for (int e = 0; e < 4; e++) {
            int idx = tid + e * 256;
            int n = idx & 63;
            int k = idx >> 6;
            Bs[k][n] = xb[(size_t)(k0 + k) * P_ + n0 + n];
        }
        __syncthreads();
        #pragma unroll
        for (int k = 0; k < 16; k++) {
            float a[4], bb[4];
            #pragma unroll
            for (int i = 0; i < 4; i++) a[i] = As[k][ty + 16 * i];
            #pragma unroll
            for (int j = 0; j < 4; j++) bb[j] = Bs[k][tx + 16 * j];
            #pragma unroll
            for (int i = 0; i < 4; i++)
                #pragma unroll
                for (int j = 0; j < 4; j++)
                    acc[i][j] += a[i] * bb[j];
        }
        __syncthreads();
    }

    float* outb = g_pw + (size_t)b * CT_ * P_;
    #pragma unroll
    for (int i = 0; i < 4; i++) {
        int co = m0 + ty + 16 * i;
        #pragma unroll
        for (int j = 0; j < 4; j++)
            outb[(size_t)co * P_ + n0 + tx + 16 * j] = acc[i][j];
    }
}

// ---------------------------------------------------------------------------
// Depthwise 3x3 conv (pad 1) + exact GELU on the bs-branch channels
// grid: (H, CT, B), block: W threads
// ---------------------------------------------------------------------------
__global__ __launch_bounds__(128) void dw_kernel(
    const float* __restrict__ w_dw,
    const float* __restrict__ w_bs_dw)
{
    const int y  = blockIdx.x;
    const int ch = blockIdx.y;
    const int b  = blockIdx.z;
    const int xo = threadIdx.x;

    const float* wp = (ch < C3_) ? (w_dw + ch * 9) : (w_bs_dw + (ch - C3_) * 9);
    float w[9];
    #pragma unroll
    for (int i = 0; i < 9; i++) w[i] = wp[i];

    const float* in = g_pw + ((size_t)b * CT_ + ch) * P_;
    float acc = 0.f;
    #pragma unroll
    for (int dy = -1; dy <= 1; dy++) {
        int yy = y + dy;
        if (yy < 0 || yy >= HH_) continue;
        #pragma unroll
        for (int dx = -1; dx <= 1; dx++) {
            int xx = xo + dx;
            if (xx < 0 || xx >= WW_) continue;
            acc += w[(dy + 1) * 3 + (dx + 1)] * in[yy * WW_ + xx];
        }
    }
    if (ch >= C3_) {
        // exact GELU
        acc = 0.5f * acc * (1.0f + erff(acc * 0.70710678118654752f));
    }
    g_dw[((size_t)b * CT_ + ch) * P_ + y * WW_ + xo] = acc;
}

// ---------------------------------------------------------------------------
// L2 norms of q and k rows (over 16384 spatial elements)
// grid: 2*B*C blocks (q then k), 256 threads
// ---------------------------------------------------------------------------
__global__ __launch_bounds__(256) void norm_kernel()
{
    const int bid = blockIdx.x;           // 0..3071
    const int isk = bid >= B_ * C_;
    const int v   = isk ? bid - B_ * C_ : bid;
    const int b   = v / C_, c = v % C_;
    const float* src = g_dw + ((size_t)b * CT_ + (isk ? C_ + c : c)) * P_;

    float s = 0.f;
    for (int i = threadIdx.x; i < P_; i += 256) {
        float t = src[i];
        s += t * t;
    }
    __shared__ float red[256];
    red[threadIdx.x] = s;
    __syncthreads();
    for (int off = 128; off > 0; off >>= 1) {
        if (threadIdx.x < off) red[threadIdx.x] += red[threadIdx.x + off];
        __syncthreads();
    }
    if (threadIdx.x == 0) g_norms[bid] = fmaxf(sqrtf(red[0]), 1e-12f);
}

// ---------------------------------------------------------------------------
// Attention logits, split-K (deterministic two-pass):
// grid: (16 splits, 32 bh), 256 threads, each thread 3x3 of the 48x48 tile
// ---------------------------------------------------------------------------
__global__ __launch_bounds__(256) void attn_part_kernel()
{
    const int s  = blockIdx.x;   // 0..15
    const int bh = blockIdx.y;   // 0..31
    const int b = bh >> 3, h = bh & 7;

    const float* qb = g_dw + ((size_t)b * CT_ + h * CH_) * P_ + s * 1024;
    const float* kb = g_dw + ((size_t)b * CT_ + C_ + h * CH_) * P_ + s * 1024;

    __shared__ float qs[48][65];
    __shared__ float ks[48][65];

    const int tid = threadIdx.x;
    const int tx = tid & 15, ty = tid >> 4;
    const int i0 = ty * 3, j0 = tx * 3;
    float acc[3][3] = {};

    for (int p0 = 0; p0 < 1024; p0 += 64) {
        #pragma unroll
        for (int e = 0; e < 12; e++) {
            int idx = tid + e * 256;   // 0..3071
            int row = idx >> 6, col = idx & 63;
            qs[row][col] = qb[(size_t)row * P_ + p0 + col];
            ks[row][col] = kb[(size_t)row * P_ + p0 + col];
        }
        __syncthreads();
        #pragma unroll 16
        for (int p = 0; p < 64; p++) {
            float a0 = qs[i0][p], a1 = qs[i0 + 1][p], a2 = qs[i0 + 2][p];
            float b0 = ks[j0][p], b1 = ks[j0 + 1][p], b2 = ks[j0 + 2][p];
            acc[0][0] += a0 * b0; acc[0][1] += a0 * b1; acc[0][2] += a0 * b2;
            acc[1][0] += a1 * b0; acc[1][1] += a1 * b1; acc[1][2] += a1 * b2;
            acc[2][0] += a2 * b0; acc[2][1] += a2 * b1; acc[2][2] += a2 * b2;
        }
        __syncthreads();
    }

    float* out = g_part + ((size_t)bh * SPLITS_ + s) * (CH_ * CH_);
    #pragma unroll
    for (int i = 0; i < 3; i++)
        #pragma unroll
        for (int j = 0; j < 3; j++)
            out[(i0 + i) * CH_ + j0 + j] = acc[i][j];
}

// ---------------------------------------------------------------------------
// Softmax rows (with normalization by q/k norms and scale)
// grid: (48, 32), 64 threads
// ---------------------------------------------------------------------------
__global__ __launch_bounds__(64) void softmax_kernel()
{
    const int i  = blockIdx.x;   // row 0..47
    const int bh = blockIdx.y;   // 0..31
    const int b = bh >> 3, h = bh & 7;
    const int j = threadIdx.x;   // 0..63

    float val = 0.f;
    float logit = -1e30f;
    if (j < CH_) {
        float sum = 0.f;
        #pragma unroll
        for (int s = 0; s < SPLITS_; s++)
            sum += g_part[((size_t)bh * SPLITS_ + s) * (CH_ * CH_) + i * CH_ + j];
        float nq = g_norms[b * C_ + h * CH_ + i];
        float nk = g_norms[B_ * C_ + b * C_ + h * CH_ + j];
        val = sum / (nq * nk) * SCALE_;
        logit = val;
    }
    __shared__ float red[64];
    red[j] = logit;
    __syncthreads();
    for (int off = 32; off > 0; off >>= 1) {
        if (j < off) red[j] = fmaxf(red[j], red[j + off]);
        __syncthreads();
    }
    float mx = red[0];
    __syncthreads();
    float e = (j < CH_) ? expf(val - mx) : 0.f;
    red[j] = e;
    __syncthreads();
    for (int off = 32; off > 0; off >>= 1) {
        if (j < off) red[j] += red[j + off];
        __syncthreads();
    }
    if (j < CH_) g_attn[(size_t)bh * CH_ * CH_ + i * CH_ + j] = e / red[0];
}

// ---------------------------------------------------------------------------
// out = attn @ V : grid (128 pixel-blocks, 32 bh), 128 threads (one pixel each)
// ---------------------------------------------------------------------------
__global__ __launch_bounds__(128) void av_kernel()
{
    const int pb = blockIdx.x;   // 0..127
    const int bh = blockIdx.y;   // 0..31
    const int b = bh >> 3, h = bh & 7;
    const int p = pb * 128 + threadIdx.x;

    __shared__ float at[CH_ * CH_];
    for (int idx = threadIdx.x; idx < CH_ * CH_; idx += 128)
        at[idx] = g_attn[(size_t)bh * CH_ * CH_ + idx];
    __syncthreads();

    const float* vb = g_dw + ((size_t)b * CT_ + 2 * C_ + h * CH_) * P_ + p;
    float v[CH_];
    #pragma unroll
    for (int d = 0; d < CH_; d++) v[d] = vb[(size_t)d * P_];

    float* ob = g_attnout + ((size_t)b * C_ + h * CH_) * P_ + p;
    #pragma unroll 4
    for (int c = 0; c < CH_; c++) {
        float acc = 0.f;
        #pragma unroll
        for (int d = 0; d < CH_; d++) acc += at[c * CH_ + d] * v[d];
        ob[(size_t)c * P_] = acc;
    }
}

// ---------------------------------------------------------------------------
// Projection 1x1 conv GEMM: out[384 x 16384] = Wproj[384 x 768] * cat(attnout,y)
// ---------------------------------------------------------------------------
__global__ __launch_bounds__(256) void gemm_proj_kernel(
    const float* __restrict__ wproj,
    float* __restrict__ out)
{
    const int b  = blockIdx.z;
    const int m0 = blockIdx.y * 64;
    const int n0 = blockIdx.x * 64;
    const int tid = threadIdx.x;
    const int tx = tid & 15, ty = tid >> 4;

    __shared__ float As[16][64];
    __shared__ float Bs[16][64];

    float acc[4][4] = {};

    for (int k0 = 0; k0 < 2 * C_; k0 += 16) {
        #pragma unroll
        for (int e = 0; e < 4; e++) {
            int idx = tid + e * 256;
            int k = idx & 15;
            int m = idx >> 4;
            As[k][m] = wproj[(m0 + m) * (2 * C_) + k0 + k];
        }
        #pragma unroll
        for (int e = 0; e < 4; e++) {
            int idx = tid + e * 256;
            int n = idx & 63;
            int k = idx >> 6;
            int row = k0 + k;
            const float* src = (row < C_)
                ? (g_attnout + ((size_t)b * C_ + row) * P_)
                : (g_dw + ((size_t)b * CT_ + C3_ + (row - C_)) * P_);
            Bs[k][n] = src[n0 + n];
        }
        __syncthreads();
        #pragma unroll
        for (int k = 0; k < 16; k++) {
            float a[4], bb[4];
            #pragma unroll
            for (int i = 0; i < 4; i++) a[i] = As[k][ty + 16 * i];
            #pragma unroll
            for (int j = 0; j < 4; j++) bb[j] = Bs[k][tx + 16 * j];
            #pragma unroll
            for (int i = 0; i < 4; i++)
                #pragma unroll
                for (int j = 0; j < 4; j++)
                    acc[i][j] += a[i] * bb[j];
        }
        __syncthreads();
    }

    float* outb = out + (size_t)b * C_ * P_;
    #pragma unroll
    for (int i = 0; i < 4; i++) {
        int co = m0 + ty + 16 * i;
        #pragma unroll
        for (int j = 0; j < 4; j++)
            outb[(size_t)co * P_ + n0 + tx + 16 * j] = acc[i][j];
    }
}

// ---------------------------------------------------------------------------
extern "C" void kernel_launch(void* const* d_in, const int* in_sizes, int n_in,
                              void* d_out, int out_size)
{
    const float* x       = (const float*)d_in[0];
    const float* w_qkv   = (const float*)d_in[1];
    const float* w_dw    = (const float*)d_in[2];
    const float* w_proj  = (const float*)d_in[3];
    const float* w_bs_pw = (const float*)d_in[4];
    const float* w_bs_dw = (const float*)d_in[5];
    float* out = (float*)d_out;

    // 1) fused pointwise (qkv + bs) GEMM
    gemm_pw_kernel<<<dim3(P_ / 64, CT_ / 64, B_), 256>>>(x, w_qkv, w_bs_pw);
    // 2) depthwise 3x3 (+GELU on bs channels)
    dw_kernel<<<dim3(HH_, CT_, B_), 128>>>(w_dw, w_bs_dw);
    // 3) q/k L2 norms
    norm_kernel<<<2 * B_ * C_, 256>>>();
    // 4) attention logits (split-K partials)
    attn_part_kernel<<<dim3(SPLITS_, BH_), 256>>>();
    // 5) softmax with normalization
    softmax_kernel<<<dim3(CH_, BH_), 64>>>();
    // 6) attn @ V
    av_kernel<<<dim3(P_ / 128, BH_), 128>>>();
    // 7) projection GEMM -> output
    gemm_proj_kernel<<<dim3(P_ / 64, C_ / 64, B_), 256>>>(w_proj, out);
}

// round 2
// speedup vs baseline: 2.0640x; 2.0640x over previous
#include <cuda_runtime.h>
#include <cuda_bf16.h>
#include <math.h>

// Problem constants
#define B_    4
#define C_    384
#define C3_   1152
#define CT_   1536        // 1152 qkv + 384 bs
#define HH_   128
#define WW_   128
#define P_    16384       // H*W
#define HEADS_ 8
#define CH_   48
#define BH_   32          // B*HEADS
#define SPLITS_ 16
#define SCALE_ 0.14433756729740643f  // 1/sqrt(48)

// Scratch (static device allocations; no cudaMalloc allowed)
__device__ float g_pw[(size_t)B_ * CT_ * P_];       // pointwise output
__device__ float g_dw[(size_t)B_ * CT_ * P_];       // depthwise output (q,k,v,y)
__device__ float g_attnout[(size_t)B_ * C_ * P_];   // attn @ V
__device__ float g_part[(size_t)BH_ * SPLITS_ * CH_ * CH_]; // split-K partials
__device__ float g_norms[2 * B_ * C_];              // q norms then k norms
__device__ float g_attn[(size_t)BH_ * CH_ * CH_];   // softmaxed attention
__device__ float g_wA[(size_t)C_ * CT_];            // transposed fused pw weights [k][co]
__device__ float g_wP[(size_t)2 * C_ * C_];         // transposed proj weights [k][co]

// ---------------------------------------------------------------------------
// f32x2 helpers (FFMA2 — only reachable via PTX)
// ---------------------------------------------------------------------------
__device__ __forceinline__ unsigned long long dup_f32x2(float x) {
    unsigned long long r;
    asm("mov.b64 %0, {%1, %1};" : "=l"(r) : "f"(x));
    return r;
}
__device__ __forceinline__ void fma_f32x2(unsigned long long& d,
                                          unsigned long long a,
                                          unsigned long long b) {
    asm("fma.rn.f32x2 %0, %1, %2, %0;" : "+l"(d) : "l"(a), "l"(b));
}
__device__ __forceinline__ float f2lo(unsigned long long v) {
    return __uint_as_float((unsigned)v);
}
__device__ __forceinline__ float f2hi(unsigned long long v) {
    return __uint_as_float((unsigned)(v >> 32));
}

// ---------------------------------------------------------------------------
// Weight transpose: g_wA[k][co] (fused qkv+bs), g_wP[k][co]
// ---------------------------------------------------------------------------
__global__ __launch_bounds__(256) void transpose_w_kernel(
    const float* __restrict__ w_qkv,
    const float* __restrict__ w_bs_pw,
    const float* __restrict__ w_proj)
{
    int idx = blockIdx.x * 256 + threadIdx.x;
    const int nA = C_ * CT_;          // 589824
    const int nP = 2 * C_ * C_;       // 294912
    if (idx < nA) {
        int k  = idx / CT_;
        int co = idx % CT_;
        float v = (co < C3_) ? w_qkv[co * C_ + k]
                             : w_bs_pw[(co - C3_) * C_ + k];
        g_wA[idx] = v;
    } else if (idx < nA + nP) {
        int j  = idx - nA;
        int k  = j / C_;
        int co = j % C_;
        g_wP[j] = w_proj[co * (2 * C_) + k];
    }
}

// ---------------------------------------------------------------------------
// FFMA2 GEMM: out[M x P] = Wt^T * B, tile 128M x 64N x 32K, 256 threads,
// microtile 8M x 4N per thread with M-paired f32x2 accumulators.
// MODE 0: pointwise (B = x, Wt = g_wA, M = CT_, K = C_, out = g_pw)
// MODE 1: proj      (B = concat(attnout, y), Wt = g_wP, M = C_, K = 2C_, out)
// ---------------------------------------------------------------------------
template <int MODE>
__global__ __launch_bounds__(256) void gemm_f32x2_kernel(
    const float* __restrict__ x, float* __restrict__ outp)
{
    const int b   = blockIdx.z;
    const int m0  = blockIdx.y * 128;
    const int n0  = blockIdx.x * 64;
    const int tid = threadIdx.x;
    const int tx  = tid & 15;          // N group (4 cols)
    const int ty  = tid >> 4;          // M group (8 rows)

    const int Kdim = (MODE == 0) ? C_ : 2 * C_;
    const int Mdim = (MODE == 0) ? CT_ : C_;
    const float* Wt = (MODE == 0) ? g_wA : g_wP;

    __shared__ float As[32][128];
    __shared__ float Bs[32][64];

    unsigned long long acc[4][4];
    #pragma unroll
    for (int i = 0; i < 4; i++)
        #pragma unroll
        for (int j = 0; j < 4; j++) acc[i][j] = 0ull;

    for (int k0 = 0; k0 < Kdim; k0 += 32) {
        // A tile: 32x128 floats = 1024 float4, 4 per thread
        #pragma unroll
        for (int e = 0; e < 4; e++) {
            int idx = tid + e * 256;
            int k   = idx >> 5;
            int m4  = (idx & 31) * 4;
            *(float4*)&As[k][m4] =
                *(const float4*)&Wt[(size_t)(k0 + k) * Mdim + m0 + m4];
        }
        // B tile: 32x64 floats = 512 float4, 2 per thread
        #pragma unroll
        for (int e = 0; e < 2; e++) {
            int idx = tid + e * 256;
            int k   = idx >> 4;
            int n4  = (idx & 15) * 4;
            int row = k0 + k;
            const float* src;
            if (MODE == 0) {
                src = x + ((size_t)b * C_ + row) * P_;
            } else {
                src = (row < C_)
                    ? (g_attnout + ((size_t)b * C_ + row) * P_)
                    : (g_dw + ((size_t)b * CT_ + C3_ + (row - C_)) * P_);
            }
            *(float4*)&Bs[k][n4] = *(const float4*)&src[n0 + n4];
        }
        __syncthreads();

        #pragma unroll
        for (int k = 0; k < 32; k++) {
            // 8 M values as 4 f32x2 pairs (two 16B shared loads)
            double2 a01 = *(const double2*)&As[k][ty * 8];
            double2 a23 = *(const double2*)&As[k][ty * 8 + 4];
            unsigned long long ap[4];
            ap[0] = __double_as_longlong(a01.x);
            ap[1] = __double_as_longlong(a01.y);
            ap[2] = __double_as_longlong(a23.x);
            ap[3] = __double_as_longlong(a23.y);
            float4 bv = *(const float4*)&Bs[k][tx * 4];
            unsigned long long bd[4];
            bd[0] = dup_f32x2(bv.x); bd[1] = dup_f32x2(bv.y);
            bd[2] = dup_f32x2(bv.z); bd[3] = dup_f32x2(bv.w);
            #pragma unroll
            for (int i = 0; i < 4; i++) {
                fma_f32x2(acc[i][0], ap[i], bd[0]);
                fma_f32x2(acc[i][1], ap[i], bd[1]);
                fma_f32x2(acc[i][2], ap[i], bd[2]);
                fma_f32x2(acc[i][3], ap[i], bd[3]);
            }
        }
        __syncthreads();
    }

    // Epilogue: 8 rows, each a float4 over this thread's 4 columns
    float* outb = outp + (size_t)b * Mdim * P_;
    #pragma unroll
    for (int i = 0; i < 4; i++) {
        int mlo = m0 + ty * 8 + 2 * i;
        float4 vlo = make_float4(f2lo(acc[i][0]), f2lo(acc[i][1]),
                                 f2lo(acc[i][2]), f2lo(acc[i][3]));
        float4 vhi = make_float4(f2hi(acc[i][0]), f2hi(acc[i][1]),
                                 f2hi(acc[i][2]), f2hi(acc[i][3]));
        *(float4*)&outb[(size_t)mlo * P_ + n0 + tx * 4]       = vlo;
        *(float4*)&outb[(size_t)(mlo + 1) * P_ + n0 + tx * 4] = vhi;
    }
}

// ---------------------------------------------------------------------------
// Depthwise 3x3 conv (pad 1) + exact GELU on the bs-branch channels
// ---------------------------------------------------------------------------
__global__ __launch_bounds__(128) void dw_kernel(
    const float* __restrict__ w_dw,
    const float* __restrict__ w_bs_dw)
{
    const int y  = blockIdx.x;
    const int ch = blockIdx.y;
    const int b  = blockIdx.z;
    const int xo = threadIdx.x;

    const float* wp = (ch < C3_) ? (w_dw + ch * 9) : (w_bs_dw + (ch - C3_) * 9);
    float w[9];
    #pragma unroll
    for (int i = 0; i < 9; i++) w[i] = wp[i];

    const float* in = g_pw + ((size_t)b * CT_ + ch) * P_;
    float acc = 0.f;
    #pragma unroll
    for (int dy = -1; dy <= 1; dy++) {
        int yy = y + dy;
        if (yy < 0 || yy >= HH_) continue;
        #pragma unroll
        for (int dx = -1; dx <= 1; dx++) {
            int xx = xo + dx;
            if (xx < 0 || xx >= WW_) continue;
            acc += w[(dy + 1) * 3 + (dx + 1)] * in[yy * WW_ + xx];
        }
    }
    if (ch >= C3_) {
        acc = 0.5f * acc * (1.0f + erff(acc * 0.70710678118654752f));
    }
    g_dw[((size_t)b * CT_ + ch) * P_ + y * WW_ + xo] = acc;
}

// ---------------------------------------------------------------------------
// L2 norms of q and k rows (over 16384 spatial elements)
// ---------------------------------------------------------------------------
__global__ __launch_bounds__(256) void norm_kernel()
{
    const int bid = blockIdx.x;           // 0..3071
    const int isk = bid >= B_ * C_;
    const int v   = isk ? bid - B_ * C_ : bid;
    const int b   = v / C_, c = v % C_;
    const float* src = g_dw + ((size_t)b * CT_ + (isk ? C_ + c : c)) * P_;

    float s = 0.f;
    for (int i = threadIdx.x; i < P_; i += 256) {
        float t = src[i];
        s += t * t;
    }
    __shared__ float red[256];
    red[threadIdx.x] = s;
    __syncthreads();
    for (int off = 128; off > 0; off >>= 1) {
        if (threadIdx.x < off) red[threadIdx.x] += red[threadIdx.x + off];
        __syncthreads();
    }
    if (threadIdx.x == 0) g_norms[bid] = fmaxf(sqrtf(red[0]), 1e-12f);
}

// ---------------------------------------------------------------------------
// Attention logits, split-K partials
// ---------------------------------------------------------------------------
__global__ __launch_bounds__(256) void attn_part_kernel()
{
    const int s  = blockIdx.x;   // 0..15
    const int bh = blockIdx.y;   // 0..31
    const int b = bh >> 3, h = bh & 7;

    const float* qb = g_dw + ((size_t)b * CT_ + h * CH_) * P_ + s * 1024;
    const float* kb = g_dw + ((size_t)b * CT_ + C_ + h * CH_) * P_ + s * 1024;

    __shared__ float qs[48][65];
    __shared__ float ks[48][65];

    const int tid = threadIdx.x;
    const int tx = tid & 15, ty = tid >> 4;
    const int i0 = ty * 3, j0 = tx * 3;
    float acc[3][3] = {};

    for (int p0 = 0; p0 < 1024; p0 += 64) {
        #pragma unroll
        for (int e = 0; e < 12; e++) {
            int idx = tid + e * 256;
            int row = idx >> 6, col = idx & 63;
            qs[row][col] = qb[(size_t)row * P_ + p0 + col];
            ks[row][col] = kb[(size_t)row * P_ + p0 + col];
        }
        __syncthreads();
        #pragma unroll 16
        for (int p = 0; p < 64; p++) {
            float a0 = qs[i0][p], a1 = qs[i0 + 1][p], a2 = qs[i0 + 2][p];
            float b0 = ks[j0][p], b1 = ks[j0 + 1][p], b2 = ks[j0 + 2][p];
            acc[0][0] += a0 * b0; acc[0][1] += a0 * b1; acc[0][2] += a0 * b2;
            acc[1][0] += a1 * b0; acc[1][1] += a1 * b1; acc[1][2] += a1 * b2;
            acc[2][0] += a2 * b0; acc[2][1] += a2 * b1; acc[2][2] += a2 * b2;
        }
        __syncthreads();
    }

    float* out = g_part + ((size_t)bh * SPLITS_ + s) * (CH_ * CH_);
    #pragma unroll
    for (int i = 0; i < 3; i++)
        #pragma unroll
        for (int j = 0; j < 3; j++)
            out[(i0 + i) * CH_ + j0 + j] = acc[i][j];
}

// ---------------------------------------------------------------------------
// Softmax rows (with normalization by q/k norms and scale)
// ---------------------------------------------------------------------------
__global__ __launch_bounds__(64) void softmax_kernel()
{
    const int i  = blockIdx.x;   // row 0..47
    const int bh = blockIdx.y;   // 0..31
    const int b = bh >> 3, h = bh & 7;
    const int j = threadIdx.x;   // 0..63

    float val = 0.f;
    float logit = -1e30f;
    if (j < CH_) {
        float sum = 0.f;
        #pragma unroll
        for (int s = 0; s < SPLITS_; s++)
            sum += g_part[((size_t)bh * SPLITS_ + s) * (CH_ * CH_) + i * CH_ + j];
        float nq = g_norms[b * C_ + h * CH_ + i];
        float nk = g_norms[B_ * C_ + b * C_ + h * CH_ + j];
        val = sum / (nq * nk) * SCALE_;
        logit = val;
    }
    __shared__ float red[64];
    red[j] = logit;
    __syncthreads();
    for (int off = 32; off > 0; off >>= 1) {
        if (j < off) red[j] = fmaxf(red[j], red[j + off]);
        __syncthreads();
    }
    float mx = red[0];
    __syncthreads();
    float e = (j < CH_) ? expf(val - mx) : 0.f;
    red[j] = e;
    __syncthreads();
    for (int off = 32; off > 0; off >>= 1) {
        if (j < off) red[j] += red[j + off];
        __syncthreads();
    }
    if (j < CH_) g_attn[(size_t)bh * CH_ * CH_ + i * CH_ + j] = e / red[0];
}

// ---------------------------------------------------------------------------
// out = attn @ V
// ---------------------------------------------------------------------------
__global__ __launch_bounds__(128) void av_kernel()
{
    const int pb = blockIdx.x;   // 0..127
    const int bh = blockIdx.y;   // 0..31
    const int b = bh >> 3, h = bh & 7;
    const int p = pb * 128 + threadIdx.x;

    __shared__ float at[CH_ * CH_];
    for (int idx = threadIdx.x; idx < CH_ * CH_; idx += 128)
        at[idx] = g_attn[(size_t)bh * CH_ * CH_ + idx];
    __syncthreads();

    const float* vb = g_dw + ((size_t)b * CT_ + 2 * C_ + h * CH_) * P_ + p;
    float v[CH_];
    #pragma unroll
    for (int d = 0; d < CH_; d++) v[d] = vb[(size_t)d * P_];

    float* ob = g_attnout + ((size_t)b * C_ + h * CH_) * P_ + p;
    #pragma unroll 4
    for (int c = 0; c < CH_; c++) {
        float acc = 0.f;
        #pragma unroll
        for (int d = 0; d < CH_; d++) acc += at[c * CH_ + d] * v[d];
        ob[(size_t)c * P_] = acc;
    }
}

// ---------------------------------------------------------------------------
extern "C" void kernel_launch(void* const* d_in, const int* in_sizes, int n_in,
                              void* d_out, int out_size)
{
    const float* x       = (const float*)d_in[0];
    const float* w_qkv   = (const float*)d_in[1];
    const float* w_dw    = (const float*)d_in[2];
    const float* w_proj  = (const float*)d_in[3];
    const float* w_bs_pw = (const float*)d_in[4];
    const float* w_bs_dw = (const float*)d_in[5];
    float* out = (float*)d_out;

    // 0) weight transpose (coalesced GEMM A-tiles)
    {
        int total = C_ * CT_ + 2 * C_ * C_;
        transpose_w_kernel<<<(total + 255) / 256, 256>>>(w_qkv, w_bs_pw, w_proj);
    }
    // 1) fused pointwise (qkv + bs) GEMM (FFMA2)
    {
        float* pw = nullptr; cudaGetSymbolAddress((void**)&pw, g_pw);
        gemm_f32x2_kernel<0><<<dim3(P_ / 64, CT_ / 128, B_), 256>>>(x, pw);
    }
    // 2) depthwise 3x3 (+GELU on bs channels)
    dw_kernel<<<dim3(HH_, CT_, B_), 128>>>(w_dw, w_bs_dw);
    // 3) q/k L2 norms
    norm_kernel<<<2 * B_ * C_, 256>>>();
    // 4) attention logits (split-K partials)
    attn_part_kernel<<<dim3(SPLITS_, BH_), 256>>>();
    // 5) softmax with normalization
    softmax_kernel<<<dim3(CH_, BH_), 64>>>();
    // 6) attn @ V
    av_kernel<<<dim3(P_ / 128, BH_), 128>>>();
    // 7) projection GEMM (FFMA2) -> output
    gemm_f32x2_kernel<1><<<dim3(P_ / 64, C_ / 128, B_), 256>>>(nullptr, out);
}

// round 4
// speedup vs baseline: 3.5556x; 1.7227x over previous
#include <cuda_runtime.h>
#include <cuda_fp16.h>
#include <math.h>
#include <stdint.h>

// Problem constants
#define B_    4
#define C_    384
#define C3_   1152
#define CT_   1536        // 1152 qkv + 384 bs
#define HH_   128
#define WW_   128
#define P_    16384       // H*W
#define HEADS_ 8
#define CH_   48
#define BH_   32          // B*HEADS
#define SPLITS_ 16
#define SCALE_ 0.14433756729740643f  // 1/sqrt(48)

#define LDK 40            // padded K stride (halfs) in GEMM smem tiles

// Scratch (static device arrays; no cudaMalloc allowed)
__device__ float g_pw[(size_t)B_ * CT_ * P_];       // pointwise output (fp32)
__device__ float g_dw[(size_t)B_ * CT_ * P_];       // depthwise output (q,k,v,y)
__device__ float g_part[(size_t)BH_ * SPLITS_ * CH_ * CH_];
__device__ float g_norms[2 * B_ * C_];
__device__ float g_attn[(size_t)BH_ * CH_ * CH_];
// fp16 hi/lo split operands for tensor-core GEMMs (K-major)
__device__ __align__(256) __half g_wA_h[(size_t)CT_ * C_];      // [m][k] fused qkv+bs
__device__ __align__(256) __half g_wA_l[(size_t)CT_ * C_];
__device__ __align__(256) __half g_wP_h[(size_t)C_ * 2 * C_];   // [m][k] proj
__device__ __align__(256) __half g_wP_l[(size_t)C_ * 2 * C_];
__device__ __align__(256) __half g_xT_h[(size_t)B_ * P_ * C_];  // [b][p][k]
__device__ __align__(256) __half g_xT_l[(size_t)B_ * P_ * C_];
__device__ __align__(256) __half g_pT_h[(size_t)B_ * P_ * 2 * C_]; // [b][p][k]
__device__ __align__(256) __half g_pT_l[(size_t)B_ * P_ * 2 * C_];

// ---------------------------------------------------------------------------
// Helpers
// ---------------------------------------------------------------------------
__device__ __forceinline__ uint32_t smem_u32(const void* p) {
    uint32_t a;
    asm("{ .reg .u64 t; cvta.to.shared.u64 t, %1; cvt.u32.u64 %0, t; }"
        : "=r"(a) : "l"(p));
    return a;
}
__device__ __forceinline__ void cp16(uint32_t sa, const void* g) {
    asm volatile("cp.async.cg.shared.global [%0], [%1], 16;" :: "r"(sa), "l"(g));
}
#define CP_COMMIT() asm volatile("cp.async.commit_group;" ::: "memory")
#define CP_WAIT0()  asm volatile("cp.async.wait_group 0;" ::: "memory")

__device__ __forceinline__ void ldm_x4(uint32_t* r, uint32_t addr) {
    asm volatile("ldmatrix.sync.aligned.m8n8.x4.shared.b16 {%0,%1,%2,%3}, [%4];"
        : "=r"(r[0]), "=r"(r[1]), "=r"(r[2]), "=r"(r[3]) : "r"(addr));
}
__device__ __forceinline__ void mma16816(float* c, const uint32_t* a, const uint32_t* b) {
    asm volatile("mma.sync.aligned.m16n8k16.row.col.f32.f16.f16.f32 "
        "{%0,%1,%2,%3}, {%4,%5,%6,%7}, {%8,%9}, {%0,%1,%2,%3};"
        : "+f"(c[0]), "+f"(c[1]), "+f"(c[2]), "+f"(c[3])
        : "r"(a[0]), "r"(a[1]), "r"(a[2]), "r"(a[3]), "r"(b[0]), "r"(b[1]));
}

// f32x2 helpers (FFMA2)
__device__ __forceinline__ void fma_f32x2(unsigned long long& d,
                                          unsigned long long a,
                                          unsigned long long b) {
    asm("fma.rn.f32x2 %0, %1, %2, %0;" : "+l"(d) : "l"(a), "l"(b));
}
__device__ __forceinline__ float f2lo(unsigned long long v) {
    return __uint_as_float((unsigned)v);
}
__device__ __forceinline__ float f2hi(unsigned long long v) {
    return __uint_as_float((unsigned)(v >> 32));
}

__device__ __forceinline__ void split_h(float v, __half& h, __half& l) {
    h = __float2half(v);
    l = __float2half(v - __half2float(h));
}
__device__ __forceinline__ uint32_t pack_h(__half a, __half b) {
    return (uint32_t)__half_as_ushort(a) | ((uint32_t)__half_as_ushort(b) << 16);
}

// ---------------------------------------------------------------------------
// Weight convert: hi/lo fp16, native [m][k] layout
// ---------------------------------------------------------------------------
__global__ __launch_bounds__(256) void conv_w_kernel(
    const float* __restrict__ w_qkv,
    const float* __restrict__ w_bs_pw,
    const float* __restrict__ w_proj)
{
    const int nA = CT_ * C_;       // 589824
    const int nP = C_ * 2 * C_;    // 294912
    int idx = blockIdx.x * 256 + threadIdx.x;
    if (idx < nA) {
        int m = idx / C_, k = idx % C_;
        float v = (m < C3_) ? w_qkv[m * C_ + k] : w_bs_pw[(m - C3_) * C_ + k];
        __half h, l; split_h(v, h, l);
        g_wA_h[idx] = h; g_wA_l[idx] = l;
    } else if (idx < nA + nP) {
        int j = idx - nA;
        float v = w_proj[j];
        __half h, l; split_h(v, h, l);
        g_wP_h[j] = h; g_wP_l[j] = l;
    }
}

// ---------------------------------------------------------------------------
// Transpose+convert x: [b][c][p] fp32 -> [b][p][c] hi/lo fp16
// grid (P/64, C/96, B), 256 threads
// ---------------------------------------------------------------------------
__global__ __launch_bounds__(256) void pack_x_kernel(const float* __restrict__ x)
{
    __shared__ __align__(16) float s[96][68];
    const int p0  = blockIdx.x * 64;
    const int ci0 = blockIdx.y * 96;
    const int b   = blockIdx.z;
    const int tid = threadIdx.x;

    #pragma unroll
    for (int e = 0; e < 24; e++) {
        int idx = tid + e * 256;
        int row = idx >> 6, col = idx & 63;
        s[row][col] = x[((size_t)b * C_ + ci0 + row) * P_ + p0 + col];
    }
    __syncthreads();

    const int px = tid & 63, part = tid >> 6;       // 4 parts x 24 ch
    size_t base = ((size_t)b * P_ + p0 + px) * C_ + ci0 + part * 24;
    uint32_t hb[12], lb[12];
    #pragma unroll
    for (int k = 0; k < 12; k++) {
        float v0 = s[part * 24 + 2 * k][px];
        float v1 = s[part * 24 + 2 * k + 1][px];
        __half h0, l0, h1, l1;
        split_h(v0, h0, l0); split_h(v1, h1, l1);
        hb[k] = pack_h(h0, h1); lb[k] = pack_h(l0, l1);
    }
    uint4* dh = (uint4*)&g_xT_h[base];
    uint4* dl = (uint4*)&g_xT_l[base];
    #pragma unroll
    for (int q = 0; q < 3; q++) {
        dh[q] = *(uint4*)&hb[q * 4];
        dl[q] = *(uint4*)&lb[q * 4];
    }
}

// ---------------------------------------------------------------------------
// Transpose+convert y (bs branch) into proj input cols 384..767
// grid (P/64, 384/96, B), 256 threads
// ---------------------------------------------------------------------------
__global__ __launch_bounds__(256) void pack_proj_kernel()
{
    __shared__ __align__(16) float s[96][68];
    const int p0  = blockIdx.x * 64;
    const int ci0 = blockIdx.y * 96;
    const int b   = blockIdx.z;
    const int tid = threadIdx.x;

    #pragma unroll
    for (int e = 0; e < 24; e++) {
        int idx = tid + e * 256;
        int row = idx >> 6, col = idx & 63;
        s[row][col] = g_dw[((size_t)b * CT_ + C3_ + ci0 + row) * P_ + p0 + col];
    }
    __syncthreads();

    const int px = tid & 63, part = tid >> 6;
    size_t base = ((size_t)b * P_ + p0 + px) * (2 * C_) + C_ + ci0 + part * 24;
    uint32_t hb[12], lb[12];
    #pragma unroll
    for (int k = 0; k < 12; k++) {
        float v0 = s[part * 24 + 2 * k][px];
        float v1 = s[part * 24 + 2 * k + 1][px];
        __half h0, l0, h1, l1;
        split_h(v0, h0, l0); split_h(v1, h1, l1);
        hb[k] = pack_h(h0, h1); lb[k] = pack_h(l0, l1);
    }
    uint4* dh = (uint4*)&g_pT_h[base];
    uint4* dl = (uint4*)&g_pT_l[base];
    #pragma unroll
    for (int q = 0; q < 3; q++) {
        dh[q] = *(uint4*)&hb[q * 4];
        dl[q] = *(uint4*)&lb[q * 4];
    }
}

// ---------------------------------------------------------------------------
// HMMA GEMM with fp16 3-term split: D[M,N] = A[M,K] @ B[N,K]^T (fp32 accum)
// CTA tile 128x128x32, 256 threads (8 warps = 4m x 2n, 32x64 each),
// cp.async double-buffered. Tiles padded to LDK=40 halfs per row.
// MODE 0: pw  (A=wA, B=xT, M=1536, K=384, out=g_pw)
// MODE 1: proj(A=wP, B=pT, M=384,  K=768, out=d_out)
// ---------------------------------------------------------------------------
#define TILE_BYTES (128 * LDK * 2)          // 10240
#define STAGE_BYTES (4 * TILE_BYTES)        // Ah, Al, Bh, Bl
#define GEMM_SMEM (2 * STAGE_BYTES)         // 81920

template <int MODE>
__global__ __launch_bounds__(256) void gemm_mma_kernel(float* __restrict__ outp)
{
    extern __shared__ __align__(16) char S[];
    const int Kdim = (MODE == 0) ? C_ : 2 * C_;
    const int Mdim = (MODE == 0) ? CT_ : C_;
    const int b  = blockIdx.z;
    const int n0 = blockIdx.x * 128;
    const int m0 = blockIdx.y * 128;

    const __half* Ah = (MODE == 0) ? g_wA_h : g_wP_h;
    const __half* Al = (MODE == 0) ? g_wA_l : g_wP_l;
    const __half* Bh = ((MODE == 0) ? g_xT_h : g_pT_h) + (size_t)b * P_ * Kdim;
    const __half* Bl = ((MODE == 0) ? g_xT_l : g_pT_l) + (size_t)b * P_ * Kdim;

    const int tid  = threadIdx.x;
    const int lane = tid & 31, warp = tid >> 5;
    const int wm = warp >> 1, wn = warp & 1;
    const uint32_t sbase = smem_u32(S);

    float acc[2][8][4];
    #pragma unroll
    for (int mt = 0; mt < 2; mt++)
        #pragma unroll
        for (int nt = 0; nt < 8; nt++)
            #pragma unroll
            for (int q = 0; q < 4; q++) acc[mt][nt][q] = 0.f;

    const int nch = Kdim / 32;
    const int lrow = tid >> 2;          // 0..63 (x2 with e)
    const int lq   = tid & 3;

    // ---- prologue load (stage 0, chunk 0)
    {
        const __half* gp[4] = { Ah + (size_t)m0 * Kdim, Al + (size_t)m0 * Kdim,
                                Bh + (size_t)n0 * Kdim, Bl + (size_t)n0 * Kdim };
        #pragma unroll
        for (int t = 0; t < 4; t++)
            #pragma unroll
            for (int e = 0; e < 2; e++) {
                int row = lrow + e * 64;
                uint32_t sa = sbase + t * TILE_BYTES + (row * LDK + lq * 8) * 2;
                cp16(sa, gp[t] + (size_t)row * Kdim + lq * 8);
            }
        CP_COMMIT();
    }

    for (int c = 0; c < nch; c++) {
        CP_WAIT0();
        __syncthreads();

        // issue next stage load (overlaps with compute below)
        if (c + 1 < nch) {
            int k0 = (c + 1) * 32;
            int st = (c + 1) & 1;
            const __half* gp[4] = { Ah + (size_t)m0 * Kdim, Al + (size_t)m0 * Kdim,
                                    Bh + (size_t)n0 * Kdim, Bl + (size_t)n0 * Kdim };
            #pragma unroll
            for (int t = 0; t < 4; t++)
                #pragma unroll
                for (int e = 0; e < 2; e++) {
                    int row = lrow + e * 64;
                    uint32_t sa = sbase + st * STAGE_BYTES + t * TILE_BYTES
                                + (row * LDK + lq * 8) * 2;
                    cp16(sa, gp[t] + (size_t)row * Kdim + k0 + lq * 8);
                }
            CP_COMMIT();
        }

        // ---- compute on stage c&1
        const uint32_t stb = sbase + (c & 1) * STAGE_BYTES;
        const uint32_t bAh = stb;
        const uint32_t bAl = stb + TILE_BYTES;
        const uint32_t bBh = stb + 2 * TILE_BYTES;
        const uint32_t bBl = stb + 3 * TILE_BYTES;

        #pragma unroll
        for (int kk = 0; kk < 2; kk++) {
            const int ko = kk * 16 + (lane >> 4) * 8;   // half offset within row
            uint32_t a_h[2][4], a_l[2][4];
            const int ar = wm * 32 + (lane & 15);
            #pragma unroll
            for (int mt = 0; mt < 2; mt++) {
                ldm_x4(a_h[mt], bAh + ((ar + mt * 16) * LDK + ko) * 2);
                ldm_x4(a_l[mt], bAl + ((ar + mt * 16) * LDK + ko) * 2);
            }
            uint32_t b_h[8][2], b_l[8][2];
            #pragma unroll
            for (int nt2 = 0; nt2 < 4; nt2++) {
                const int br = wn * 64 + nt2 * 16 + (lane & 15);
                uint32_t r[4];
                ldm_x4(r, bBh + (br * LDK + ko) * 2);
                b_h[nt2 * 2][0] = r[0]; b_h[nt2 * 2 + 1][0] = r[1];
                b_h[nt2 * 2][1] = r[2]; b_h[nt2 * 2 + 1][1] = r[3];
                ldm_x4(r, bBl + (br * LDK + ko) * 2);
                b_l[nt2 * 2][0] = r[0]; b_l[nt2 * 2 + 1][0] = r[1];
                b_l[nt2 * 2][1] = r[2]; b_l[nt2 * 2 + 1][1] = r[3];
            }
            #pragma unroll
            for (int mt = 0; mt < 2; mt++)
                #pragma unroll
                for (int nt = 0; nt < 8; nt++) {
                    mma16816(acc[mt][nt], a_h[mt], b_h[nt]);
                    mma16816(acc[mt][nt], a_h[mt], b_l[nt]);
                    mma16816(acc[mt][nt], a_l[mt], b_h[nt]);
                }
        }
        __syncthreads();
    }

    // ---- epilogue: direct fp32 stores
    float* outb = outp + (size_t)b * Mdim * P_;
    #pragma unroll
    for (int mt = 0; mt < 2; mt++) {
        int r1 = m0 + wm * 32 + mt * 16 + (lane >> 2);
        #pragma unroll
        for (int nt = 0; nt < 8; nt++) {
            int col = n0 + wn * 64 + nt * 8 + 2 * (lane & 3);
            float2 v0 = make_float2(acc[mt][nt][0], acc[mt][nt][1]);
            float2 v1 = make_float2(acc[mt][nt][2], acc[mt][nt][3]);
            *(float2*)&outb[(size_t)r1 * P_ + col]       = v0;
            *(float2*)&outb[(size_t)(r1 + 8) * P_ + col] = v1;
        }
    }
}

// ---------------------------------------------------------------------------
// Depthwise 3x3 conv (pad 1) + exact GELU on bs channels, 16-row tiles
// grid (HH/16, CT, B), 256 threads
// ---------------------------------------------------------------------------
__global__ __launch_bounds__(256) void dw_kernel(
    const float* __restrict__ w_dw,
    const float* __restrict__ w_bs_dw)
{
    __shared__ float s[18][128];
    const int y0 = blockIdx.x * 16;
    const int ch = blockIdx.y;
    const int b  = blockIdx.z;
    const int tid = threadIdx.x;

    const float* in = g_pw + ((size_t)b * CT_ + ch) * P_;
    #pragma unroll
    for (int e = 0; e < 9; e++) {
        int idx = tid + e * 256;
        int row = idx >> 7, col = idx & 127;
        int y = y0 - 1 + row;
        s[row][col] = (y >= 0 && y < HH_) ? in[y * WW_ + col] : 0.f;
    }
    __syncthreads();

    const float* wp = (ch < C3_) ? (w_dw + ch * 9) : (w_bs_dw + (ch - C3_) * 9);
    float w[9];
    #pragma unroll
    for (int i = 0; i < 9; i++) w[i] = __ldg(&wp[i]);

    float* outc = g_dw + ((size_t)b * CT_ + ch) * P_;
    const int x = tid & 127;
    #pragma unroll
    for (int i = 0; i < 8; i++) {
        int r = 2 * i + (tid >> 7);
        const float* s0 = s[r];
        const float* s1 = s[r + 1];
        const float* s2 = s[r + 2];
        float acc = w[1] * s0[x] + w[4] * s1[x] + w[7] * s2[x];
        if (x > 0)
            acc += w[0] * s0[x - 1] + w[3] * s1[x - 1] + w[6] * s2[x - 1];
        if (x < 127)
            acc += w[2] * s0[x + 1] + w[5] * s1[x + 1] + w[8] * s2[x + 1];
        if (ch >= C3_)
            acc = 0.5f * acc * (1.0f + erff(acc * 0.70710678118654752f));
        outc[(y0 + r) * WW_ + x] = acc;
    }
}

// ---------------------------------------------------------------------------
// L2 norms of q and k rows
// ---------------------------------------------------------------------------
__global__ __launch_bounds__(256) void norm_kernel()
{
    const int bid = blockIdx.x;
    const int isk = bid >= B_ * C_;
    const int v   = isk ? bid - B_ * C_ : bid;
    const int b   = v / C_, c = v % C_;
    const float* src = g_dw + ((size_t)b * CT_ + (isk ? C_ + c : c)) * P_;

    float s = 0.f;
    for (int i = threadIdx.x; i < P_; i += 256) {
        float t = src[i];
        s += t * t;
    }
    __shared__ float red[256];
    red[threadIdx.x] = s;
    __syncthreads();
    for (int off = 128; off > 0; off >>= 1) {
        if (threadIdx.x < off) red[threadIdx.x] += red[threadIdx.x + off];
        __syncthreads();
    }
    if (threadIdx.x == 0) g_norms[bid] = fmaxf(sqrtf(red[0]), 1e-12f);
}

// ---------------------------------------------------------------------------
// Attention logits split-K partials (f32x2)
// ---------------------------------------------------------------------------
__global__ __launch_bounds__(256) void attn_part_kernel()
{
    const int s  = blockIdx.x;   // 0..15
    const int bh = blockIdx.y;   // 0..31
    const int b = bh >> 3, h = bh & 7;

    const float* qb = g_dw + ((size_t)b * CT_ + h * CH_) * P_ + s * 1024;
    const float* kb = g_dw + ((size_t)b * CT_ + C_ + h * CH_) * P_ + s * 1024;

    __shared__ __align__(16) float qs[48][66];
    __shared__ __align__(16) float ks[48][66];

    const int tid = threadIdx.x;
    const int tx = tid & 15, ty = tid >> 4;
    const int i0 = ty * 3, j0 = tx * 3;
    unsigned long long acc[3][3];
    #pragma unroll
    for (int i = 0; i < 3; i++)
        #pragma unroll
        for (int jj = 0; jj < 3; jj++) acc[i][jj] = 0ull;

    for (int p0 = 0; p0 < 1024; p0 += 64) {
        #pragma unroll
        for (int e = 0; e < 12; e++) {
            int idx = tid + e * 256;
            int row = idx >> 6, col = idx & 63;
            qs[row][col] = qb[(size_t)row * P_ + p0 + col];
            ks[row][col] = kb[(size_t)row * P_ + p0 + col];
        }
        __syncthreads();
        #pragma unroll 8
        for (int p = 0; p < 64; p += 2) {
            unsigned long long a0 = __double_as_longlong(*(const double*)&qs[i0][p]);
            unsigned long long a1 = __double_as_longlong(*(const double*)&qs[i0 + 1][p]);
            unsigned long long a2 = __double_as_longlong(*(const double*)&qs[i0 + 2][p]);
            unsigned long long b0 = __double_as_longlong(*(const double*)&ks[j0][p]);
            unsigned long long b1 = __double_as_longlong(*(const double*)&ks[j0 + 1][p]);
            unsigned long long b2 = __double_as_longlong(*(const double*)&ks[j0 + 2][p]);
            fma_f32x2(acc[0][0], a0, b0); fma_f32x2(acc[0][1], a0, b1); fma_f32x2(acc[0][2], a0, b2);
            fma_f32x2(acc[1][0], a1, b0); fma_f32x2(acc[1][1], a1, b1); fma_f32x2(acc[1][2], a1, b2);
            fma_f32x2(acc[2][0], a2, b0); fma_f32x2(acc[2][1], a2, b1); fma_f32x2(acc[2][2], a2, b2);
        }
        __syncthreads();
    }

    float* out = g_part + ((size_t)bh * SPLITS_ + s) * (CH_ * CH_);
    #pragma unroll
    for (int i = 0; i < 3; i++)
        #pragma unroll
        for (int jj = 0; jj < 3; jj++)
            out[(i0 + i) * CH_ + j0 + jj] = f2lo(acc[i][jj]) + f2hi(acc[i][jj]);
}

// ---------------------------------------------------------------------------
// Softmax rows (with normalization by q/k norms and scale)
// ---------------------------------------------------------------------------
__global__ __launch_bounds__(64) void softmax_kernel()
{
    const int i  = blockIdx.x;
    const int bh = blockIdx.y;
    const int b = bh >> 3, h = bh & 7;
    const int j = threadIdx.x;

    float val = 0.f;
    float logit = -1e30f;
    if (j < CH_) {
        float sum = 0.f;
        #pragma unroll
        for (int s = 0; s < SPLITS_; s++)
            sum += g_part[((size_t)bh * SPLITS_ + s) * (CH_ * CH_) + i * CH_ + j];
        float nq = g_norms[b * C_ + h * CH_ + i];
        float nk = g_norms[B_ * C_ + b * C_ + h * CH_ + j];
        val = sum / (nq * nk) * SCALE_;
        logit = val;
    }
    __shared__ float red[64];
    red[j] = logit;
    __syncthreads();
    for (int off = 32; off > 0; off >>= 1) {
        if (j < off) red[j] = fmaxf(red[j], red[j + off]);
        __syncthreads();
    }
    float mx = red[0];
    __syncthreads();
    float e = (j < CH_) ? expf(val - mx) : 0.f;
    red[j] = e;
    __syncthreads();
    for (int off = 32; off > 0; off >>= 1) {
        if (j < off) red[j] += red[j + off];
        __syncthreads();
    }
    if (j < CH_) g_attn[(size_t)bh * CH_ * CH_ + i * CH_ + j] = e / red[0];
}

// ---------------------------------------------------------------------------
// out = attn @ V, written directly as hi/lo fp16 into proj input cols 0..383
// grid (P/128, BH), 128 threads (one pixel each)
// ---------------------------------------------------------------------------
__global__ __launch_bounds__(128) void av_kernel()
{
    const int pb = blockIdx.x;
    const int bh = blockIdx.y;
    const int b = bh >> 3, h = bh & 7;
    const int p = pb * 128 + threadIdx.x;

    __shared__ float at[CH_ * CH_];
    for (int idx = threadIdx.x; idx < CH_ * CH_; idx += 128)
        at[idx] = g_attn[(size_t)bh * CH_ * CH_ + idx];
    __syncthreads();

    const float* vb = g_dw + ((size_t)b * CT_ + 2 * C_ + h * CH_) * P_ + p;
    float v[CH_];
    #pragma unroll
    for (int d = 0; d < CH_; d++) v[d] = vb[(size_t)d * P_];

    uint32_t hb[24], lb[24];
    #pragma unroll 4
    for (int cp = 0; cp < 24; cp++) {
        float a0 = 0.f, a1 = 0.f;
        #pragma unroll
        for (int d = 0; d < CH_; d++) {
            a0 += at[(2 * cp) * CH_ + d] * v[d];
            a1 += at[(2 * cp + 1) * CH_ + d] * v[d];
        }
        __half h0, l0, h1, l1;
        split_h(a0, h0, l0); split_h(a1, h1, l1);
        hb[cp] = pack_h(h0, h1); lb[cp] = pack_h(l0, l1);
    }

    size_t base = ((size_t)b * P_ + p) * (2 * C_) + h * CH_;
    uint4* dh = (uint4*)&g_pT_h[base];
    uint4* dl = (uint4*)&g_pT_l[base];
    #pragma unroll
    for (int q = 0; q < 6; q++) {
        dh[q] = *(uint4*)&hb[q * 4];
        dl[q] = *(uint4*)&lb[q * 4];
    }
}

// ---------------------------------------------------------------------------
extern "C" void kernel_launch(void* const* d_in, const int* in_sizes, int n_in,
                              void* d_out, int out_size)
{
    const float* x       = (const float*)d_in[0];
    const float* w_qkv   = (const float*)d_in[1];
    const float* w_dw    = (const float*)d_in[2];
    const float* w_proj  = (const float*)d_in[3];
    const float* w_bs_pw = (const float*)d_in[4];
    const float* w_bs_dw = (const float*)d_in[5];
    float* out = (float*)d_out;

    cudaFuncSetAttribute(gemm_mma_kernel<0>,
                         cudaFuncAttributeMaxDynamicSharedMemorySize, GEMM_SMEM);
    cudaFuncSetAttribute(gemm_mma_kernel<1>,
                         cudaFuncAttributeMaxDynamicSharedMemorySize, GEMM_SMEM);

    float* pw = nullptr;
    cudaGetSymbolAddress((void**)&pw, g_pw);

    // 0) weight convert + x transpose/convert
    {
        int total = CT_ * C_ + C_ * 2 * C_;
        conv_w_kernel<<<(total + 255) / 256, 256>>>(w_qkv, w_bs_pw, w_proj);
    }
    pack_x_kernel<<<dim3(P_ / 64, C_ / 96, B_), 256>>>(x);
    // 1) fused pointwise GEMM (HMMA fp16 3-term split)
    gemm_mma_kernel<0><<<dim3(P_ / 128, CT_ / 128, B_), 256, GEMM_SMEM>>>(pw);
    // 2) depthwise 3x3 (+GELU on bs channels)
    dw_kernel<<<dim3(HH_ / 16, CT_, B_), 256>>>(w_dw, w_bs_dw);
    // 3) q/k L2 norms
    norm_kernel<<<2 * B_ * C_, 256>>>();
    // 4) attention logits (split-K partials, f32x2)
    attn_part_kernel<<<dim3(SPLITS_, BH_), 256>>>();
    // 5) softmax with normalization
    softmax_kernel<<<dim3(CH_, BH_), 64>>>();
    // 6) attn @ V -> proj input cols 0..383 (fp16 hi/lo)
    av_kernel<<<dim3(P_ / 128, BH_), 128>>>();
    // 6b) y branch -> proj input cols 384..767
    pack_proj_kernel<<<dim3(P_ / 64, C_ / 96, B_), 256>>>();
    // 7) projection GEMM (HMMA) -> output
    gemm_mma_kernel<1><<<dim3(P_ / 128, C_ / 128, B_), 256, GEMM_SMEM>>>(out);
}